// round 6
// baseline (speedup 1.0000x reference)
#include <cuda_runtime.h>
#include <cstdint>
#include <mma.h>

using namespace nvcuda;

#define R_DIM 600
#define D_DIM 240
#define N_DIM 840
#define H_DIM 8
#define C_DIM 64
#define HC 512
#define E_DIM 20000
#define ME 20840            // E + N (self loops)
#define F_CNN 1242
#define NEG 0.2f
#define MAXDEG 512

// padded dims for guard-free FC pipeline
#define KP 1248             // 39 * 32
#define NP 1280             // 10 * 128
#define MP 896              // 7 * 128

// ---------------- scratch (device globals; no allocation allowed) ----------
__device__ float g_xl[N_DIM * HC];
__device__ float g_xr[N_DIM * HC];
__device__ int   g_offset[N_DIM + 1];
__device__ int   g_csr[ME];
__device__ float g_cat[MP * NP];       // padded, tf32-rounded
__device__ float g_wp[KP * NP];        // padded Wfc, tf32-rounded
__device__ float g_feat[N_DIM * F_CNN];

// ---------------- cp.async helpers -------------------------------------------
__device__ __forceinline__ void cp16(float* dst_smem, const float* src) {
    unsigned int d = (unsigned int)__cvta_generic_to_shared(dst_smem);
    asm volatile("cp.async.cg.shared.global [%0], [%1], 16;\n" :: "r"(d), "l"(src) : "memory");
}
__device__ __forceinline__ void cp_commit() {
    asm volatile("cp.async.commit_group;\n" ::: "memory");
}
template<int W> __device__ __forceinline__ void cp_wait() {
    asm volatile("cp.async.wait_group %0;\n" :: "n"(W) : "memory");
}

// ---------------- edge helpers ------------------------------------------------
__device__ __forceinline__ int edge_dst(const int* ei, int e) {
    return (e < E_DIM) ? ei[E_DIM + e] : (e - E_DIM);
}
__device__ __forceinline__ int edge_src(const int* ei, int e) {
    return (e < E_DIM) ? ei[e] : (e - E_DIM);
}

// ---------------- pad kernel: Wfc -> g_wp (tf32), zero-pad g_cat rows --------
__global__ void k_pad(const float* __restrict__ Wfc) {
    int idx = blockIdx.x * 256 + threadIdx.x;
    const int T1 = KP * NP;
    if (idx < T1) {
        int r = idx / NP, c = idx % NP;
        float v = (r < F_CNN && c < F_CNN) ? Wfc[(size_t)r * F_CNN + c] : 0.f;
        g_wp[idx] = wmma::__float_to_tf32(v);
    } else {
        int j = idx - T1;
        if (j < (MP - N_DIM) * NP)
            g_cat[(size_t)N_DIM * NP + j] = 0.f;
    }
}

// ---------------- graph prep: count + scan + scatter, single block ----------
__global__ void k_prep(const int* __restrict__ ei) {
    __shared__ int scnt[N_DIM];
    __shared__ int soff[1024];
    int t = threadIdx.x;                       // 1024 threads
    if (t < N_DIM) scnt[t] = 0;
    __syncthreads();
    for (int e = t; e < ME; e += 1024) atomicAdd(&scnt[edge_dst(ei, e)], 1);
    __syncthreads();
    soff[t] = (t < N_DIM) ? scnt[t] : 0;
    __syncthreads();
    for (int o = 1; o < 1024; o <<= 1) {
        int v = soff[t];
        int a = (t >= o) ? soff[t - o] : 0;
        __syncthreads();
        soff[t] = v + a;
        __syncthreads();
    }
    if (t < N_DIM) g_offset[t + 1] = soff[t];
    if (t == 0)    g_offset[0] = 0;
    if (t < N_DIM) scnt[t] = (t == 0) ? 0 : soff[t - 1];
    __syncthreads();
    for (int e = t; e < ME; e += 1024) {
        int d = edge_dst(ei, e);
        int pos = atomicAdd(&scnt[d], 1);
        g_csr[pos] = e;
    }
}

// ---------------- fused: h = feat@W, then xl/xr = h@W_l/W_r (8 nodes/block) --
__global__ void k_hx(const float* __restrict__ met, const float* __restrict__ dis,
                     const float* __restrict__ Wrna, const float* __restrict__ Wdis,
                     const float* __restrict__ Wl, const float* __restrict__ bl,
                     const float* __restrict__ Wr, const float* __restrict__ br) {
    __shared__ float srows[8][600];
    __shared__ float sh[8][C_DIM];
    int b = blockIdx.x;                  // 0..104 ; blocks 0..74 rna, 75..104 dis
    int tid = threadIdx.x;               // 512
    bool rna = (b < 75);
    int r0 = rna ? b * 8 : R_DIM + (b - 75) * 8;
    int K  = rna ? R_DIM : D_DIM;
    const float* src = rna ? met : dis;
    int lr0 = rna ? b * 8 : (b - 75) * 8;

    for (int i = tid; i < 8 * K; i += 512) {
        int g = i / K, k = i % K;
        srows[g][k] = src[(size_t)(lr0 + g) * K + k];
    }
    __syncthreads();

    {   // phase 1: h rows
        int g = tid >> 6, c = tid & 63;
        const float* W = rna ? Wrna : Wdis;
        float acc = 0.f;
        #pragma unroll 4
        for (int k = 0; k < K; k++) acc += srows[g][k] * W[k * C_DIM + c];
        sh[g][c] = acc;
    }
    __syncthreads();

    {   // phase 2: xl/xr for 8 nodes
        int j = tid;
        float al[8] = {0,0,0,0,0,0,0,0};
        float ar[8] = {0,0,0,0,0,0,0,0};
        #pragma unroll 4
        for (int k = 0; k < C_DIM; k++) {
            float wl = Wl[k * HC + j];
            float wr = Wr[k * HC + j];
            #pragma unroll
            for (int g = 0; g < 8; g++) {
                float hv = sh[g][k];
                al[g] += hv * wl;
                ar[g] += hv * wr;
            }
        }
        float bjl = bl[j], bjr = br[j];
        #pragma unroll
        for (int g = 0; g < 8; g++) {
            g_xl[(size_t)(r0 + g) * HC + j] = al[g] + bjl;
            g_xr[(size_t)(r0 + g) * HC + j] = ar[g] + bjr;
        }
    }
}

// ---------------- conv dot (compile-time kw) ----------------------------------
template<int KW>
__device__ __forceinline__ float conv_dot(const float* __restrict__ sx, int p,
                                          const float* __restrict__ w) {
    float acc = 0.f;
    #pragma unroll
    for (int h = 0; h < H_DIM; h++) {
        #pragma unroll
        for (int k = 0; k < KW; k++)
            acc += sx[h * C_DIM + p + k] * w[h * KW + k];
    }
    return acc;
}

// ---------------- fused GAT (logits + softmax + aggregate) + CNN -------------
__global__ void k_gatconv(const int* __restrict__ ei, const float* __restrict__ att,
                          const float* __restrict__ gb,
                          const float* __restrict__ w1,  const float* __restrict__ b1,
                          const float* __restrict__ w4,  const float* __restrict__ b4,
                          const float* __restrict__ w16, const float* __restrict__ b16,
                          const float* __restrict__ w32, const float* __restrict__ b32) {
    __shared__ float sxr[HC];
    __shared__ float satt[HC];
    __shared__ float swt[2544];
    __shared__ float sbias[24];
    __shared__ float slog[H_DIM][MAXDEG];
    __shared__ int   ssrc[MAXDEG];
    __shared__ float sm[H_DIM], sinv[H_DIM];
    __shared__ float sres[HC];
    int n = blockIdx.x;
    int tid = threadIdx.x;               // 256
    int warp = tid >> 5, lane = tid & 31;

    sxr[tid]        = g_xr[(size_t)n * HC + tid];
    sxr[tid + 256]  = g_xr[(size_t)n * HC + tid + 256];
    satt[tid]       = att[tid];
    satt[tid + 256] = att[tid + 256];
    for (int i = tid; i < 2544; i += 256)
        swt[i] = (i < 48) ? w1[i] : (i < 240) ? w4[i - 48]
               : (i < 1008) ? w16[i - 240] : w32[i - 1008];
    if (tid < 24)
        sbias[tid] = (tid < 6) ? b1[tid] : (tid < 12) ? b4[tid - 6]
                   : (tid < 18) ? b16[tid - 12] : b32[tid - 18];

    int beg = g_offset[n], deg = g_offset[n + 1] - beg;
    __syncthreads();

    // pass A: logits, warp-per-edge, into smem
    const float4* sxr4  = (const float4*)sxr;
    const float4* satt4 = (const float4*)satt;
    int half = lane >> 4;
    for (int base = 0; base < deg; base += 8) {
        int i = base + warp;
        if (i < deg) {
            int e = g_csr[beg + i];
            int src = edge_src(ei, e);
            if (lane == 0) ssrc[i] = src;
            const float4* pl4 = (const float4*)(g_xl + (size_t)src * HC);
            float4 a[4];
            #pragma unroll
            for (int q = 0; q < 4; q++) a[q] = pl4[lane + 32 * q];
            #pragma unroll
            for (int q = 0; q < 4; q++) {
                int f = lane + 32 * q;
                float4 r = sxr4[f];
                float4 w = satt4[f];
                float vx = a[q].x + r.x; vx = vx > 0.f ? vx : NEG * vx;
                float vy = a[q].y + r.y; vy = vy > 0.f ? vy : NEG * vy;
                float vz = a[q].z + r.z; vz = vz > 0.f ? vz : NEG * vz;
                float vw = a[q].w + r.w; vw = vw > 0.f ? vw : NEG * vw;
                float t = vx * w.x + vy * w.y + vz * w.z + vw * w.w;
                #pragma unroll
                for (int o = 8; o > 0; o >>= 1) t += __shfl_xor_sync(0xffffffffu, t, o);
                if ((lane & 15) == 0) slog[2 * q + half][i] = t;
            }
        }
    }
    __syncthreads();

    // stats: warp h handles head h
    {
        int h = warp;
        float m = -1e30f;
        for (int i = lane; i < deg; i += 32) m = fmaxf(m, slog[h][i]);
        #pragma unroll
        for (int o = 16; o > 0; o >>= 1) m = fmaxf(m, __shfl_xor_sync(0xffffffffu, m, o));
        float s = 0.f;
        for (int i = lane; i < deg; i += 32) s += __expf(slog[h][i] - m);
        #pragma unroll
        for (int o = 16; o > 0; o >>= 1) s += __shfl_xor_sync(0xffffffffu, s, o);
        if (lane == 0) { sm[h] = m; sinv[h] = 1.f / (s + 1e-16f); }
    }
    __syncthreads();

    // alphas in place
    for (int i = tid; i < deg * H_DIM; i += 256) {
        int hh = i / deg, ii = i % deg;
        slog[hh][ii] = __expf(slog[hh][ii] - sm[hh]) * sinv[hh];
    }
    __syncthreads();

    // pass B: aggregate, thread t owns channels t and t+256
    float acc0 = gb[tid], acc1 = gb[tid + 256];
    int h0 = tid >> 6, h1 = (tid + 256) >> 6;
    for (int i = 0; i < deg; i++) {
        const float* px = g_xl + (size_t)ssrc[i] * HC;
        acc0 += slog[h0][i] * px[tid];
        acc1 += slog[h1][i] * px[tid + 256];
    }
    sres[tid] = acc0;
    sres[tid + 256] = acc1;
    __syncthreads();

    // conv branches on smem row -> padded g_cat row (tf32-rounded)
    float* crow = g_cat + (size_t)n * NP;
    for (int o = tid; o < NP; o += 256) {
        float v = 0.f;
        if (o < 384)       { int oc = o >> 6;          int p = o & 63;        v = sbias[oc]      + conv_dot<1>(sres, p, swt + oc * 8); }
        else if (o < 750)  { int q = o - 384;  int oc = q / 61; int p = q % 61; v = sbias[6 + oc]  + conv_dot<4>(sres, p, swt + 48 + oc * 32); }
        else if (o < 1044) { int q = o - 750;  int oc = q / 49; int p = q % 49; v = sbias[12 + oc] + conv_dot<16>(sres, p, swt + 240 + oc * 128); }
        else if (o < 1242) { int q = o - 1044; int oc = q / 33; int p = q % 33; v = sbias[18 + oc] + conv_dot<32>(sres, p, swt + 1008 + oc * 256); }
        crow[o] = wmma::__float_to_tf32(fmaxf(v, 0.f));
    }
}

// ---------------- FC GEMM (tf32 wmma + cp.async double buffer) ---------------
#define BM 128
#define BN 128
#define BK 32
#define LDA 36
#define LDB 132
#define NT 39   // KP / BK
#define STG (BM * LDA + BK * LDB)   // 4608 + 4224 = 8832 floats
#define FC_SMEM (2 * STG * 4)       // 70656 bytes

extern __shared__ float fcbuf[];

__global__ void k_fc(const float* __restrict__ bfc) {
    int tid = threadIdx.x;             // 256
    int warp = tid >> 5;
    int wm = warp >> 1;                // 0..3 -> 32-row strip
    int wn = warp & 1;                 // 0..1 -> 64-col strip
    int m0 = blockIdx.y * BM;
    int n0 = blockIdx.x * BN;

    wmma::fragment<wmma::accumulator, 16, 16, 8, float> acc[2][4];
    #pragma unroll
    for (int i = 0; i < 2; i++)
        #pragma unroll
        for (int j = 0; j < 4; j++) wmma::fill_fragment(acc[i][j], 0.f);

    auto load_stage = [&](int s, int kt) {
        float* As = fcbuf + s * STG;
        float* Bs = As + BM * LDA;
        int k0 = kt * BK;
        #pragma unroll
        for (int t = 0; t < 4; t++) {          // A: 1024 float4
            int i = tid + t * 256;
            int r = i >> 3, c4 = i & 7;
            cp16(As + r * LDA + c4 * 4, g_cat + (size_t)(m0 + r) * NP + k0 + c4 * 4);
        }
        #pragma unroll
        for (int t = 0; t < 4; t++) {          // B: 1024 float4
            int i = tid + t * 256;
            int r = i >> 5, c4 = i & 31;
            cp16(Bs + r * LDB + c4 * 4, g_wp + (size_t)(k0 + r) * NP + n0 + c4 * 4);
        }
        cp_commit();
    };

    load_stage(0, 0);
    for (int t = 0; t < NT; t++) {
        int s = t & 1;
        if (t + 1 < NT) { load_stage(s ^ 1, t + 1); cp_wait<1>(); }
        else            { cp_wait<0>(); }
        __syncthreads();
        const float* As = fcbuf + s * STG;
        const float* Bs = As + BM * LDA;
        #pragma unroll
        for (int kk = 0; kk < BK; kk += 8) {
            wmma::fragment<wmma::matrix_a, 16, 16, 8, wmma::precision::tf32, wmma::row_major> a0, a1;
            wmma::load_matrix_sync(a0, As + (wm * 32) * LDA + kk, LDA);
            wmma::load_matrix_sync(a1, As + (wm * 32 + 16) * LDA + kk, LDA);
            #pragma unroll
            for (int j = 0; j < 4; j++) {
                wmma::fragment<wmma::matrix_b, 16, 16, 8, wmma::precision::tf32, wmma::row_major> bf;
                wmma::load_matrix_sync(bf, Bs + kk * LDB + wn * 64 + j * 16, LDB);
                wmma::mma_sync(acc[0][j], a0, bf, acc[0][j]);
                wmma::mma_sync(acc[1][j], a1, bf, acc[1][j]);
            }
        }
        __syncthreads();
    }

    float* Cs = fcbuf;                          // 128 x 132
    #pragma unroll
    for (int i = 0; i < 2; i++)
        #pragma unroll
        for (int j = 0; j < 4; j++)
            wmma::store_matrix_sync(Cs + (wm * 32 + i * 16) * LDB + wn * 64 + j * 16,
                                    acc[i][j], LDB, wmma::mem_row_major);
    __syncthreads();
    #pragma unroll
    for (int t = 0; t < 64; t++) {               // 128*128/256
        int i = tid + t * 256;
        int r = i >> 7, c = i & 127;
        int gr = m0 + r, gc = n0 + c;
        if (gr < N_DIM && gc < F_CNN) {
            float v = Cs[r * LDB + c] + bfc[gc];
            g_feat[(size_t)gr * F_CNN + gc] = v > 0.f ? v : 0.f;
        }
    }
}

// ---------------- pairs: outer product write (HBM-bound) + labels ------------
#define NF2 621   // 1242/2

__global__ void k_pairs(float* __restrict__ out, const float* __restrict__ rel,
                        size_t labels_off) {
    __shared__ float2 srna[NF2];
    int i = blockIdx.x;                 // 0..599
    int tid = threadIdx.x;              // 640
    const float2* rrow = (const float2*)(g_feat + (size_t)i * F_CNN);
    if (tid < NF2) srna[tid] = rrow[tid];
    __syncthreads();

    if (blockIdx.y == 0 && tid >= NF2 && tid < NF2 + 16) {
        int l = tid - NF2;
        for (int j = l; j < D_DIM; j += 16)
            out[labels_off + (size_t)i * D_DIM + j] = rel[(size_t)i * D_DIM + j];
    }
    if (tid >= NF2) return;
    float2 rv = srna[tid];
    int j0 = blockIdx.y * 48;
    #pragma unroll 2
    for (int j = j0; j < j0 + 48; j++) {
        const float2* drow = (const float2*)(g_feat + (size_t)(R_DIM + j) * F_CNN);
        float2 dv = drow[tid];
        float2 o; o.x = rv.x * dv.x; o.y = rv.y * dv.y;
        __stcs((float2*)(out + (size_t)(i * D_DIM + j) * F_CNN) + tid, o);
    }
}

// ---------------- launch ------------------------------------------------------
extern "C" void kernel_launch(void* const* d_in, const int* in_sizes, int n_in,
                              void* d_out, int out_size) {
    const int*   ei   = (const int*)d_in[0];
    const float* met  = (const float*)d_in[1];
    const float* dis  = (const float*)d_in[2];
    const float* rel  = (const float*)d_in[3];
    const float* Wr   = (const float*)d_in[4];
    const float* Wd   = (const float*)d_in[5];
    const float* Wl   = (const float*)d_in[6];
    const float* bl   = (const float*)d_in[7];
    const float* Wrt  = (const float*)d_in[8];
    const float* br   = (const float*)d_in[9];
    const float* att  = (const float*)d_in[10];
    const float* gb   = (const float*)d_in[11];
    const float* c1w  = (const float*)d_in[12];
    const float* c1b  = (const float*)d_in[13];
    const float* c4w  = (const float*)d_in[14];
    const float* c4b  = (const float*)d_in[15];
    const float* c16w = (const float*)d_in[16];
    const float* c16b = (const float*)d_in[17];
    const float* c32w = (const float*)d_in[18];
    const float* c32b = (const float*)d_in[19];
    const float* Wfc  = (const float*)d_in[20];
    const float* bfc  = (const float*)d_in[21];
    float* out = (float*)d_out;

    static int smem_set = 0;
    if (!smem_set) {
        cudaFuncSetAttribute(k_fc, cudaFuncAttributeMaxDynamicSharedMemorySize, FC_SMEM);
        smem_set = 1;
    }

    int pad_total = KP * NP + (MP - N_DIM) * NP;
    k_pad<<<(pad_total + 255) / 256, 256>>>(Wfc);
    k_prep<<<1, 1024>>>(ei);
    k_hx<<<105, 512>>>(met, dis, Wr, Wd, Wl, bl, Wrt, br);
    k_gatconv<<<N_DIM, 256>>>(ei, att, gb, c1w, c1b, c4w, c4b, c16w, c16b, c32w, c32b);
    k_fc<<<dim3(NP / BN, MP / BM), 256, FC_SMEM>>>(bfc);
    size_t labels_off = (size_t)out_size - (size_t)R_DIM * D_DIM;
    k_pairs<<<dim3(R_DIM, 5), 640>>>(out, rel, labels_off);
}

// round 7
// speedup vs baseline: 1.0184x; 1.0184x over previous
#include <cuda_runtime.h>
#include <cstdint>
#include <mma.h>

using namespace nvcuda;

#define R_DIM 600
#define D_DIM 240
#define N_DIM 840
#define H_DIM 8
#define C_DIM 64
#define HC 512
#define E_DIM 20000
#define ME 20840            // E + N (self loops)
#define F_CNN 1242
#define NEG 0.2f

// padded dims for guard-free FC pipeline
#define KP 1248             // 39 * 32
#define NP 1280             // 10 * 128
#define MP 896              // 7 * 128

// ---------------- scratch (device globals; no allocation allowed) ----------
__device__ float g_xl[N_DIM * HC];
__device__ float g_xr[N_DIM * HC];
__device__ float g_logits[ME * H_DIM];
__device__ int   g_offset[N_DIM + 1];
__device__ int   g_csr[ME];
__device__ float g_cat[MP * NP];       // padded, tf32-rounded
__device__ float g_wp[KP * NP];        // padded Wfc, tf32-rounded
__device__ float g_feat[N_DIM * F_CNN];

// ---------------- cp.async helpers -------------------------------------------
__device__ __forceinline__ void cp16(float* dst_smem, const float* src) {
    unsigned int d = (unsigned int)__cvta_generic_to_shared(dst_smem);
    asm volatile("cp.async.cg.shared.global [%0], [%1], 16;\n" :: "r"(d), "l"(src) : "memory");
}
__device__ __forceinline__ void cp_commit() {
    asm volatile("cp.async.commit_group;\n" ::: "memory");
}
template<int W> __device__ __forceinline__ void cp_wait() {
    asm volatile("cp.async.wait_group %0;\n" :: "n"(W) : "memory");
}

// ---------------- edge helpers ------------------------------------------------
__device__ __forceinline__ int edge_dst(const int* ei, int e) {
    return (e < E_DIM) ? ei[E_DIM + e] : (e - E_DIM);
}
__device__ __forceinline__ int edge_src(const int* ei, int e) {
    return (e < E_DIM) ? ei[e] : (e - E_DIM);
}

// ---------------- pad kernel: Wfc -> g_wp (tf32), zero-pad g_cat rows --------
__global__ void k_pad(const float* __restrict__ Wfc) {
    int idx = blockIdx.x * 256 + threadIdx.x;
    const int T1 = KP * NP;
    if (idx < T1) {
        int r = idx / NP, c = idx % NP;
        float v = (r < F_CNN && c < F_CNN) ? Wfc[(size_t)r * F_CNN + c] : 0.f;
        g_wp[idx] = wmma::__float_to_tf32(v);
    } else {
        int j = idx - T1;
        if (j < (MP - N_DIM) * NP)
            g_cat[(size_t)N_DIM * NP + j] = 0.f;
    }
}

// ---------------- graph prep: count + scan + scatter, single block ----------
__global__ void k_prep(const int* __restrict__ ei) {
    __shared__ int scnt[N_DIM];
    __shared__ int soff[1024];
    int t = threadIdx.x;                       // 1024 threads
    if (t < N_DIM) scnt[t] = 0;
    __syncthreads();
    for (int e = t; e < ME; e += 1024) atomicAdd(&scnt[edge_dst(ei, e)], 1);
    __syncthreads();
    soff[t] = (t < N_DIM) ? scnt[t] : 0;
    __syncthreads();
    for (int o = 1; o < 1024; o <<= 1) {
        int v = soff[t];
        int a = (t >= o) ? soff[t - o] : 0;
        __syncthreads();
        soff[t] = v + a;
        __syncthreads();
    }
    if (t < N_DIM) g_offset[t + 1] = soff[t];
    if (t == 0)    g_offset[0] = 0;
    if (t < N_DIM) scnt[t] = (t == 0) ? 0 : soff[t - 1];
    __syncthreads();
    for (int e = t; e < ME; e += 1024) {
        int d = edge_dst(ei, e);
        int pos = atomicAdd(&scnt[d], 1);
        g_csr[pos] = e;
    }
}

// ---------------- fused: h = feat@W, then xl/xr = h@W_l/W_r (8 nodes/block) --
__global__ void k_hx(const float* __restrict__ met, const float* __restrict__ dis,
                     const float* __restrict__ Wrna, const float* __restrict__ Wdis,
                     const float* __restrict__ Wl, const float* __restrict__ bl,
                     const float* __restrict__ Wr, const float* __restrict__ br) {
    __shared__ float srows[8][600];
    __shared__ float sh[8][C_DIM];
    int b = blockIdx.x;                  // 0..104 ; blocks 0..74 rna, 75..104 dis
    int tid = threadIdx.x;               // 512
    bool rna = (b < 75);
    int r0 = rna ? b * 8 : R_DIM + (b - 75) * 8;
    int K  = rna ? R_DIM : D_DIM;
    const float* src = rna ? met : dis;
    int lr0 = rna ? b * 8 : (b - 75) * 8;

    for (int i = tid; i < 8 * K; i += 512) {
        int g = i / K, k = i % K;
        srows[g][k] = src[(size_t)(lr0 + g) * K + k];
    }
    __syncthreads();

    {   // phase 1: h rows
        int g = tid >> 6, c = tid & 63;
        const float* W = rna ? Wrna : Wdis;
        float acc = 0.f;
        #pragma unroll 4
        for (int k = 0; k < K; k++) acc += srows[g][k] * W[k * C_DIM + c];
        sh[g][c] = acc;
    }
    __syncthreads();

    {   // phase 2: xl/xr for 8 nodes
        int j = tid;
        float al[8] = {0,0,0,0,0,0,0,0};
        float ar[8] = {0,0,0,0,0,0,0,0};
        #pragma unroll 4
        for (int k = 0; k < C_DIM; k++) {
            float wl = Wl[k * HC + j];
            float wr = Wr[k * HC + j];
            #pragma unroll
            for (int g = 0; g < 8; g++) {
                float hv = sh[g][k];
                al[g] += hv * wl;
                ar[g] += hv * wr;
            }
        }
        float bjl = bl[j], bjr = br[j];
        #pragma unroll
        for (int g = 0; g < 8; g++) {
            g_xl[(size_t)(r0 + g) * HC + j] = al[g] + bjl;
            g_xr[(size_t)(r0 + g) * HC + j] = ar[g] + bjr;
        }
    }
}

// ---------------- edge logits: one warp per edge, batched float4 loads -------
__global__ void k_logits(const int* __restrict__ ei, const float* __restrict__ att) {
    __shared__ float4 satt[128];
    int tid = threadIdx.x;                // 256
    if (tid < 128) satt[tid] = ((const float4*)att)[tid];
    __syncthreads();
    int e = (blockIdx.x * 256 + tid) >> 5;
    if (e >= ME) return;
    int lane = tid & 31;
    int src = edge_src(ei, e);
    int dst = edge_dst(ei, e);
    const float4* pl4 = (const float4*)(g_xl + (size_t)src * HC);
    const float4* pr4 = (const float4*)(g_xr + (size_t)dst * HC);

    // batch all 8 loads up front (MLP)
    float4 a[4], b[4];
    #pragma unroll
    for (int q = 0; q < 4; q++) { a[q] = pl4[lane + 32 * q]; b[q] = pr4[lane + 32 * q]; }

    int half = lane >> 4;
    #pragma unroll
    for (int q = 0; q < 4; q++) {
        float4 w = satt[lane + 32 * q];
        float vx = a[q].x + b[q].x; vx = vx > 0.f ? vx : NEG * vx;
        float vy = a[q].y + b[q].y; vy = vy > 0.f ? vy : NEG * vy;
        float vz = a[q].z + b[q].z; vz = vz > 0.f ? vz : NEG * vz;
        float vw = a[q].w + b[q].w; vw = vw > 0.f ? vw : NEG * vw;
        float t = vx * w.x + vy * w.y + vz * w.z + vw * w.w;
        #pragma unroll
        for (int o = 8; o > 0; o >>= 1) t += __shfl_xor_sync(0xffffffffu, t, o);
        if ((lane & 15) == 0) g_logits[e * H_DIM + 2 * q + half] = t;
    }
}

// ---------------- conv dot (compile-time kw) ----------------------------------
template<int KW>
__device__ __forceinline__ float conv_dot(const float* __restrict__ sx, int p,
                                          const float* __restrict__ w) {
    float acc = 0.f;
    #pragma unroll
    for (int h = 0; h < H_DIM; h++) {
        #pragma unroll
        for (int k = 0; k < KW; k++)
            acc += sx[h * C_DIM + p + k] * w[h * KW + k];
    }
    return acc;
}

// ---------------- fused GAT aggregate + CNN branches --------------------------
__global__ void k_gatconv(const int* __restrict__ ei, const float* __restrict__ gb,
                          const float* __restrict__ w1,  const float* __restrict__ b1,
                          const float* __restrict__ w4,  const float* __restrict__ b4,
                          const float* __restrict__ w16, const float* __restrict__ b16,
                          const float* __restrict__ w32, const float* __restrict__ b32) {
    __shared__ float swt[2544];
    __shared__ float sbias[24];
    __shared__ float sm[H_DIM], sinv[H_DIM];
    __shared__ int   sedge[64], ssrc[64];
    __shared__ float salpha[8 * 64];
    __shared__ float sres[HC];
    int n = blockIdx.x;
    int tid = threadIdx.x;               // 256
    int h = tid >> 5, lane = tid & 31;

    for (int i = tid; i < 2544; i += 256)
        swt[i] = (i < 48) ? w1[i] : (i < 240) ? w4[i - 48]
               : (i < 1008) ? w16[i - 240] : w32[i - 1008];
    if (tid < 24)
        sbias[tid] = (tid < 6) ? b1[tid] : (tid < 12) ? b4[tid - 6]
                   : (tid < 18) ? b16[tid - 12] : b32[tid - 18];

    int beg = g_offset[n], end = g_offset[n + 1], deg = end - beg;

    // phase A: per-head max and sum (warp h)
    float m = -1e30f;
    for (int i = beg + lane; i < end; i += 32)
        m = fmaxf(m, g_logits[g_csr[i] * H_DIM + h]);
    #pragma unroll
    for (int o = 16; o > 0; o >>= 1) m = fmaxf(m, __shfl_xor_sync(0xffffffffu, m, o));
    float s = 0.f;
    for (int i = beg + lane; i < end; i += 32)
        s += __expf(g_logits[g_csr[i] * H_DIM + h] - m);
    #pragma unroll
    for (int o = 16; o > 0; o >>= 1) s += __shfl_xor_sync(0xffffffffu, s, o);
    if (lane == 0) { sm[h] = m; sinv[h] = 1.f / (s + 1e-16f); }
    __syncthreads();

    // phase B: aggregate, thread t owns channels t and t+256
    float acc0 = gb[tid], acc1 = gb[tid + 256];
    int h0 = tid >> 6, h1 = (tid + 256) >> 6;
    for (int c0 = 0; c0 < deg; c0 += 64) {
        int nch = min(64, deg - c0);
        if (tid < nch) {
            int e = g_csr[beg + c0 + tid];
            sedge[tid] = e;
            ssrc[tid] = edge_src(ei, e);
        }
        __syncthreads();
        {
            int i = tid & 63, hh = tid >> 6;
            if (i < nch) salpha[hh * 64 + i] =
                __expf(g_logits[sedge[i] * H_DIM + hh] - sm[hh]) * sinv[hh];
            i = (tid + 256) & 63; hh = (tid + 256) >> 6;
            if (i < nch) salpha[hh * 64 + i] =
                __expf(g_logits[sedge[i] * H_DIM + hh] - sm[hh]) * sinv[hh];
        }
        __syncthreads();
        for (int i = 0; i < nch; i++) {
            const float* px = g_xl + (size_t)ssrc[i] * HC;
            acc0 += salpha[h0 * 64 + i] * px[tid];
            acc1 += salpha[h1 * 64 + i] * px[tid + 256];
        }
        __syncthreads();
    }
    sres[tid] = acc0;
    sres[tid + 256] = acc1;
    __syncthreads();

    // phase C: conv branches on smem row -> padded g_cat row (tf32-rounded)
    float* crow = g_cat + (size_t)n * NP;
    for (int o = tid; o < NP; o += 256) {
        float v = 0.f;
        if (o < 384)       { int oc = o >> 6;          int p = o & 63;        v = sbias[oc]      + conv_dot<1>(sres, p, swt + oc * 8); }
        else if (o < 750)  { int q = o - 384;  int oc = q / 61; int p = q % 61; v = sbias[6 + oc]  + conv_dot<4>(sres, p, swt + 48 + oc * 32); }
        else if (o < 1044) { int q = o - 750;  int oc = q / 49; int p = q % 49; v = sbias[12 + oc] + conv_dot<16>(sres, p, swt + 240 + oc * 128); }
        else if (o < 1242) { int q = o - 1044; int oc = q / 33; int p = q % 33; v = sbias[18 + oc] + conv_dot<32>(sres, p, swt + 1008 + oc * 256); }
        crow[o] = wmma::__float_to_tf32(fmaxf(v, 0.f));
    }
}

// ---------------- FC GEMM (tf32 wmma + cp.async double buffer, 128x128) ------
#define BM 128
#define BN 128
#define BK 32
#define LDA 36
#define LDB 132
#define NT 39   // KP / BK
#define STG (BM * LDA + BK * LDB)   // 4608 + 4224 = 8832 floats
#define FC_SMEM (2 * STG * 4)       // 70656 bytes

extern __shared__ float fcbuf[];

__global__ void k_fc(const float* __restrict__ bfc) {
    int tid = threadIdx.x;             // 256
    int warp = tid >> 5;
    int wm = warp >> 1;                // 0..3 -> 32-row strip
    int wn = warp & 1;                 // 0..1 -> 64-col strip
    int m0 = blockIdx.y * BM;
    int n0 = blockIdx.x * BN;

    wmma::fragment<wmma::accumulator, 16, 16, 8, float> acc[2][4];
    #pragma unroll
    for (int i = 0; i < 2; i++)
        #pragma unroll
        for (int j = 0; j < 4; j++) wmma::fill_fragment(acc[i][j], 0.f);

    auto load_stage = [&](int s, int kt) {
        float* As = fcbuf + s * STG;
        float* Bs = As + BM * LDA;
        int k0 = kt * BK;
        #pragma unroll
        for (int t = 0; t < 4; t++) {          // A: 1024 float4
            int i = tid + t * 256;
            int r = i >> 3, c4 = i & 7;
            cp16(As + r * LDA + c4 * 4, g_cat + (size_t)(m0 + r) * NP + k0 + c4 * 4);
        }
        #pragma unroll
        for (int t = 0; t < 4; t++) {          // B: 1024 float4
            int i = tid + t * 256;
            int r = i >> 5, c4 = i & 31;
            cp16(Bs + r * LDB + c4 * 4, g_wp + (size_t)(k0 + r) * NP + n0 + c4 * 4);
        }
        cp_commit();
    };

    load_stage(0, 0);
    for (int t = 0; t < NT; t++) {
        int s = t & 1;
        if (t + 1 < NT) { load_stage(s ^ 1, t + 1); cp_wait<1>(); }
        else            { cp_wait<0>(); }
        __syncthreads();
        const float* As = fcbuf + s * STG;
        const float* Bs = As + BM * LDA;
        #pragma unroll
        for (int kk = 0; kk < BK; kk += 8) {
            wmma::fragment<wmma::matrix_a, 16, 16, 8, wmma::precision::tf32, wmma::row_major> a0, a1;
            wmma::load_matrix_sync(a0, As + (wm * 32) * LDA + kk, LDA);
            wmma::load_matrix_sync(a1, As + (wm * 32 + 16) * LDA + kk, LDA);
            #pragma unroll
            for (int j = 0; j < 4; j++) {
                wmma::fragment<wmma::matrix_b, 16, 16, 8, wmma::precision::tf32, wmma::row_major> bf;
                wmma::load_matrix_sync(bf, Bs + kk * LDB + wn * 64 + j * 16, LDB);
                wmma::mma_sync(acc[0][j], a0, bf, acc[0][j]);
                wmma::mma_sync(acc[1][j], a1, bf, acc[1][j]);
            }
        }
        __syncthreads();
    }

    float* Cs = fcbuf;                          // 128 x 132
    #pragma unroll
    for (int i = 0; i < 2; i++)
        #pragma unroll
        for (int j = 0; j < 4; j++)
            wmma::store_matrix_sync(Cs + (wm * 32 + i * 16) * LDB + wn * 64 + j * 16,
                                    acc[i][j], LDB, wmma::mem_row_major);
    __syncthreads();
    #pragma unroll
    for (int t = 0; t < 64; t++) {               // 128*128/256
        int i = tid + t * 256;
        int r = i >> 7, c = i & 127;
        int gr = m0 + r, gc = n0 + c;
        if (gr < N_DIM && gc < F_CNN) {
            float v = Cs[r * LDB + c] + bfc[gc];
            g_feat[(size_t)gr * F_CNN + gc] = v > 0.f ? v : 0.f;
        }
    }
}

// ---------------- pairs: outer product write (HBM-bound) + labels ------------
#define NF2 621   // 1242/2

__global__ void k_pairs(float* __restrict__ out, const float* __restrict__ rel,
                        size_t labels_off) {
    __shared__ float2 srna[NF2];
    int i = blockIdx.x;                 // 0..599
    int tid = threadIdx.x;              // 640
    const float2* rrow = (const float2*)(g_feat + (size_t)i * F_CNN);
    if (tid < NF2) srna[tid] = rrow[tid];
    __syncthreads();

    if (blockIdx.y == 0 && tid >= NF2 && tid < NF2 + 16) {
        int l = tid - NF2;
        for (int j = l; j < D_DIM; j += 16)
            out[labels_off + (size_t)i * D_DIM + j] = rel[(size_t)i * D_DIM + j];
    }
    if (tid >= NF2) return;
    float2 rv = srna[tid];
    int j0 = blockIdx.y * 48;
    #pragma unroll 2
    for (int j = j0; j < j0 + 48; j++) {
        const float2* drow = (const float2*)(g_feat + (size_t)(R_DIM + j) * F_CNN);
        float2 dv = drow[tid];
        float2 o; o.x = rv.x * dv.x; o.y = rv.y * dv.y;
        __stcs((float2*)(out + (size_t)(i * D_DIM + j) * F_CNN) + tid, o);
    }
}

// ---------------- launch ------------------------------------------------------
extern "C" void kernel_launch(void* const* d_in, const int* in_sizes, int n_in,
                              void* d_out, int out_size) {
    const int*   ei   = (const int*)d_in[0];
    const float* met  = (const float*)d_in[1];
    const float* dis  = (const float*)d_in[2];
    const float* rel  = (const float*)d_in[3];
    const float* Wr   = (const float*)d_in[4];
    const float* Wd   = (const float*)d_in[5];
    const float* Wl   = (const float*)d_in[6];
    const float* bl   = (const float*)d_in[7];
    const float* Wrt  = (const float*)d_in[8];
    const float* br   = (const float*)d_in[9];
    const float* att  = (const float*)d_in[10];
    const float* gb   = (const float*)d_in[11];
    const float* c1w  = (const float*)d_in[12];
    const float* c1b  = (const float*)d_in[13];
    const float* c4w  = (const float*)d_in[14];
    const float* c4b  = (const float*)d_in[15];
    const float* c16w = (const float*)d_in[16];
    const float* c16b = (const float*)d_in[17];
    const float* c32w = (const float*)d_in[18];
    const float* c32b = (const float*)d_in[19];
    const float* Wfc  = (const float*)d_in[20];
    const float* bfc  = (const float*)d_in[21];
    float* out = (float*)d_out;

    static int smem_set = 0;
    if (!smem_set) {
        cudaFuncSetAttribute(k_fc, cudaFuncAttributeMaxDynamicSharedMemorySize, FC_SMEM);
        smem_set = 1;
    }

    int pad_total = KP * NP + (MP - N_DIM) * NP;
    k_pad<<<(pad_total + 255) / 256, 256>>>(Wfc);
    k_prep<<<1, 1024>>>(ei);
    k_hx<<<105, 512>>>(met, dis, Wr, Wd, Wl, bl, Wrt, br);
    k_logits<<<(ME * 32 + 255) / 256, 256>>>(ei, att);
    k_gatconv<<<N_DIM, 256>>>(ei, gb, c1w, c1b, c4w, c4b, c16w, c16b, c32w, c32b);
    k_fc<<<dim3(NP / BN, MP / BM), 256, FC_SMEM>>>(bfc);
    size_t labels_off = (size_t)out_size - (size_t)R_DIM * D_DIM;
    k_pairs<<<dim3(R_DIM, 5), 640>>>(out, rel, labels_off);
}

// round 8
// speedup vs baseline: 1.1061x; 1.0861x over previous
#include <cuda_runtime.h>
#include <cstdint>
#include <mma.h>

using namespace nvcuda;

#define R_DIM 600
#define D_DIM 240
#define N_DIM 840
#define H_DIM 8
#define C_DIM 64
#define HC 512
#define E_DIM 20000
#define ME 20840            // E + N (self loops)
#define F_CNN 1242
#define NEG 0.2f

// padded dims for guard-free FC pipeline
#define KP 1248             // 39 * 32
#define NP 1280             // 20 * 64
#define MP 896              // 7 * 128

// ---------------- scratch (device globals; no allocation allowed) ----------
__device__ float g_xl[N_DIM * HC];
__device__ float g_xr[N_DIM * HC];
__device__ float g_logits[ME * H_DIM];
__device__ int   g_offset[N_DIM + 1];
__device__ int   g_csr[ME];
__device__ float g_cat[MP * NP];       // padded, tf32-rounded
__device__ float g_wp[KP * NP];        // padded Wfc, tf32-rounded
__device__ float g_feat[N_DIM * F_CNN];

// ---------------- cp.async helpers -------------------------------------------
__device__ __forceinline__ void cp16(float* dst_smem, const float* src) {
    unsigned int d = (unsigned int)__cvta_generic_to_shared(dst_smem);
    asm volatile("cp.async.cg.shared.global [%0], [%1], 16;\n" :: "r"(d), "l"(src) : "memory");
}
__device__ __forceinline__ void cp_commit() {
    asm volatile("cp.async.commit_group;\n" ::: "memory");
}
template<int W> __device__ __forceinline__ void cp_wait() {
    asm volatile("cp.async.wait_group %0;\n" :: "n"(W) : "memory");
}

// ---------------- edge helpers ------------------------------------------------
__device__ __forceinline__ int edge_dst(const int* ei, int e) {
    return (e < E_DIM) ? ei[E_DIM + e] : (e - E_DIM);
}
__device__ __forceinline__ int edge_src(const int* ei, int e) {
    return (e < E_DIM) ? ei[e] : (e - E_DIM);
}

// ---------------- pad kernel: Wfc -> g_wp (tf32), pad g_cat, labels ----------
__global__ void k_pad(const float* __restrict__ Wfc, const float* __restrict__ rel,
                      float* __restrict__ out, size_t labels_off) {
    int idx = blockIdx.x * 256 + threadIdx.x;
    const int T1 = KP * NP;
    const int T2 = T1 + (MP - N_DIM) * NP;
    if (idx < T1) {
        int r = idx / NP, c = idx % NP;
        float v = (r < F_CNN && c < F_CNN) ? Wfc[(size_t)r * F_CNN + c] : 0.f;
        g_wp[idx] = wmma::__float_to_tf32(v);
    } else if (idx < T2) {
        g_cat[(size_t)N_DIM * NP + (idx - T1)] = 0.f;
    } else {
        int j = idx - T2;
        if (j < R_DIM * D_DIM) out[labels_off + j] = rel[j];
    }
}

// ---------------- graph prep: count + scan + scatter, single block ----------
__global__ void k_prep(const int* __restrict__ ei) {
    __shared__ int scnt[N_DIM];
    __shared__ int soff[1024];
    int t = threadIdx.x;                       // 1024 threads
    if (t < N_DIM) scnt[t] = 0;
    __syncthreads();
    for (int e = t; e < ME; e += 1024) atomicAdd(&scnt[edge_dst(ei, e)], 1);
    __syncthreads();
    soff[t] = (t < N_DIM) ? scnt[t] : 0;
    __syncthreads();
    for (int o = 1; o < 1024; o <<= 1) {
        int v = soff[t];
        int a = (t >= o) ? soff[t - o] : 0;
        __syncthreads();
        soff[t] = v + a;
        __syncthreads();
    }
    if (t < N_DIM) g_offset[t + 1] = soff[t];
    if (t == 0)    g_offset[0] = 0;
    if (t < N_DIM) scnt[t] = (t == 0) ? 0 : soff[t - 1];
    __syncthreads();
    for (int e = t; e < ME; e += 1024) {
        int d = edge_dst(ei, e);
        int pos = atomicAdd(&scnt[d], 1);
        g_csr[pos] = e;
    }
}

// ---------------- fused: h = feat@W, then xl/xr = h@W_l/W_r (8 nodes/block) --
__global__ void k_hx(const float* __restrict__ met, const float* __restrict__ dis,
                     const float* __restrict__ Wrna, const float* __restrict__ Wdis,
                     const float* __restrict__ Wl, const float* __restrict__ bl,
                     const float* __restrict__ Wr, const float* __restrict__ br) {
    __shared__ float srows[8][600];
    __shared__ float sh[8][C_DIM];
    int b = blockIdx.x;                  // 0..104 ; blocks 0..74 rna, 75..104 dis
    int tid = threadIdx.x;               // 512
    bool rna = (b < 75);
    int r0 = rna ? b * 8 : R_DIM + (b - 75) * 8;
    int K  = rna ? R_DIM : D_DIM;
    const float* src = rna ? met : dis;
    int lr0 = rna ? b * 8 : (b - 75) * 8;

    for (int i = tid; i < 8 * K; i += 512) {
        int g = i / K, k = i % K;
        srows[g][k] = src[(size_t)(lr0 + g) * K + k];
    }
    __syncthreads();

    {   // phase 1: h rows
        int g = tid >> 6, c = tid & 63;
        const float* W = rna ? Wrna : Wdis;
        float acc = 0.f;
        #pragma unroll 4
        for (int k = 0; k < K; k++) acc += srows[g][k] * W[k * C_DIM + c];
        sh[g][c] = acc;
    }
    __syncthreads();

    {   // phase 2: xl/xr for 8 nodes
        int j = tid;
        float al[8] = {0,0,0,0,0,0,0,0};
        float ar[8] = {0,0,0,0,0,0,0,0};
        #pragma unroll 4
        for (int k = 0; k < C_DIM; k++) {
            float wl = Wl[k * HC + j];
            float wr = Wr[k * HC + j];
            #pragma unroll
            for (int g = 0; g < 8; g++) {
                float hv = sh[g][k];
                al[g] += hv * wl;
                ar[g] += hv * wr;
            }
        }
        float bjl = bl[j], bjr = br[j];
        #pragma unroll
        for (int g = 0; g < 8; g++) {
            g_xl[(size_t)(r0 + g) * HC + j] = al[g] + bjl;
            g_xr[(size_t)(r0 + g) * HC + j] = ar[g] + bjr;
        }
    }
}

// ---------------- edge logits: one warp per edge, batched float4 loads -------
__global__ void k_logits(const int* __restrict__ ei, const float* __restrict__ att) {
    __shared__ float4 satt[128];
    int tid = threadIdx.x;                // 256
    if (tid < 128) satt[tid] = ((const float4*)att)[tid];
    __syncthreads();
    int e = (blockIdx.x * 256 + tid) >> 5;
    if (e >= ME) return;
    int lane = tid & 31;
    int src = edge_src(ei, e);
    int dst = edge_dst(ei, e);
    const float4* pl4 = (const float4*)(g_xl + (size_t)src * HC);
    const float4* pr4 = (const float4*)(g_xr + (size_t)dst * HC);

    float4 a[4], b[4];
    #pragma unroll
    for (int q = 0; q < 4; q++) { a[q] = pl4[lane + 32 * q]; b[q] = pr4[lane + 32 * q]; }

    int half = lane >> 4;
    #pragma unroll
    for (int q = 0; q < 4; q++) {
        float4 w = satt[lane + 32 * q];
        float vx = a[q].x + b[q].x; vx = vx > 0.f ? vx : NEG * vx;
        float vy = a[q].y + b[q].y; vy = vy > 0.f ? vy : NEG * vy;
        float vz = a[q].z + b[q].z; vz = vz > 0.f ? vz : NEG * vz;
        float vw = a[q].w + b[q].w; vw = vw > 0.f ? vw : NEG * vw;
        float t = vx * w.x + vy * w.y + vz * w.z + vw * w.w;
        #pragma unroll
        for (int o = 8; o > 0; o >>= 1) t += __shfl_xor_sync(0xffffffffu, t, o);
        if ((lane & 15) == 0) g_logits[e * H_DIM + 2 * q + half] = t;
    }
}

// ---------------- conv dot (compile-time kw) ----------------------------------
template<int KW>
__device__ __forceinline__ float conv_dot(const float* __restrict__ sx, int p,
                                          const float* __restrict__ w) {
    float acc = 0.f;
    #pragma unroll
    for (int h = 0; h < H_DIM; h++) {
        #pragma unroll
        for (int k = 0; k < KW; k++)
            acc += sx[h * C_DIM + p + k] * w[h * KW + k];
    }
    return acc;
}

// ---------------- fused GAT aggregate + CNN branches --------------------------
__global__ void k_gatconv(const int* __restrict__ ei, const float* __restrict__ gb,
                          const float* __restrict__ w1,  const float* __restrict__ b1,
                          const float* __restrict__ w4,  const float* __restrict__ b4,
                          const float* __restrict__ w16, const float* __restrict__ b16,
                          const float* __restrict__ w32, const float* __restrict__ b32) {
    __shared__ float swt[2544];
    __shared__ float sbias[24];
    __shared__ float sm[H_DIM], sinv[H_DIM];
    __shared__ int   sedge[64], ssrc[64];
    __shared__ float salpha[8 * 64];
    __shared__ float sres[HC];
    int n = blockIdx.x;
    int tid = threadIdx.x;               // 256
    int h = tid >> 5, lane = tid & 31;

    for (int i = tid; i < 2544; i += 256)
        swt[i] = (i < 48) ? w1[i] : (i < 240) ? w4[i - 48]
               : (i < 1008) ? w16[i - 240] : w32[i - 1008];
    if (tid < 24)
        sbias[tid] = (tid < 6) ? b1[tid] : (tid < 12) ? b4[tid - 6]
                   : (tid < 18) ? b16[tid - 12] : b32[tid - 18];

    int beg = g_offset[n], end = g_offset[n + 1], deg = end - beg;

    // phase A: per-head max and sum (warp h)
    float m = -1e30f;
    for (int i = beg + lane; i < end; i += 32)
        m = fmaxf(m, g_logits[g_csr[i] * H_DIM + h]);
    #pragma unroll
    for (int o = 16; o > 0; o >>= 1) m = fmaxf(m, __shfl_xor_sync(0xffffffffu, m, o));
    float s = 0.f;
    for (int i = beg + lane; i < end; i += 32)
        s += __expf(g_logits[g_csr[i] * H_DIM + h] - m);
    #pragma unroll
    for (int o = 16; o > 0; o >>= 1) s += __shfl_xor_sync(0xffffffffu, s, o);
    if (lane == 0) { sm[h] = m; sinv[h] = 1.f / (s + 1e-16f); }
    __syncthreads();

    // phase B: aggregate, thread t owns channels t and t+256
    float acc0 = gb[tid], acc1 = gb[tid + 256];
    int h0 = tid >> 6, h1 = (tid + 256) >> 6;
    for (int c0 = 0; c0 < deg; c0 += 64) {
        int nch = min(64, deg - c0);
        if (tid < nch) {
            int e = g_csr[beg + c0 + tid];
            sedge[tid] = e;
            ssrc[tid] = edge_src(ei, e);
        }
        __syncthreads();
        {
            int i = tid & 63, hh = tid >> 6;
            if (i < nch) salpha[hh * 64 + i] =
                __expf(g_logits[sedge[i] * H_DIM + hh] - sm[hh]) * sinv[hh];
            i = (tid + 256) & 63; hh = (tid + 256) >> 6;
            if (i < nch) salpha[hh * 64 + i] =
                __expf(g_logits[sedge[i] * H_DIM + hh] - sm[hh]) * sinv[hh];
        }
        __syncthreads();
        for (int i = 0; i < nch; i++) {
            const float* px = g_xl + (size_t)ssrc[i] * HC;
            acc0 += salpha[h0 * 64 + i] * px[tid];
            acc1 += salpha[h1 * 64 + i] * px[tid + 256];
        }
        __syncthreads();
    }
    sres[tid] = acc0;
    sres[tid + 256] = acc1;
    __syncthreads();

    // phase C: conv branches on smem row -> padded g_cat row (tf32-rounded)
    float* crow = g_cat + (size_t)n * NP;
    for (int o = tid; o < NP; o += 256) {
        float v = 0.f;
        if (o < 384)       { int oc = o >> 6;          int p = o & 63;        v = sbias[oc]      + conv_dot<1>(sres, p, swt + oc * 8); }
        else if (o < 750)  { int q = o - 384;  int oc = q / 61; int p = q % 61; v = sbias[6 + oc]  + conv_dot<4>(sres, p, swt + 48 + oc * 32); }
        else if (o < 1044) { int q = o - 750;  int oc = q / 49; int p = q % 49; v = sbias[12 + oc] + conv_dot<16>(sres, p, swt + 240 + oc * 128); }
        else if (o < 1242) { int q = o - 1044; int oc = q / 33; int p = q % 33; v = sbias[18 + oc] + conv_dot<32>(sres, p, swt + 1008 + oc * 256); }
        crow[o] = wmma::__float_to_tf32(fmaxf(v, 0.f));
    }
}

// ---------------- FC GEMM (tf32 wmma, 128x64, 512 threads, cp.async x2) ------
#define BM 128
#define BN 64
#define BK 32
#define LDA 36
#define LDB 68
#define NT 39   // KP / BK
#define STG (BM * LDA + BK * LDB)   // 4608 + 2176 = 6784 floats
#define FC_SMEM (2 * STG * 4)       // 54272 bytes

extern __shared__ float fcbuf[];

__global__ __launch_bounds__(512) void k_fc(const float* __restrict__ bfc) {
    int tid = threadIdx.x;             // 512
    int warp = tid >> 5;               // 0..15
    int wm = warp >> 1;                // 0..7 -> 16-row strip
    int wn = warp & 1;                 // 0..1 -> 32-col strip
    int m0 = blockIdx.y * BM;
    int n0 = blockIdx.x * BN;

    wmma::fragment<wmma::accumulator, 16, 16, 8, float> acc[2];
    wmma::fill_fragment(acc[0], 0.f);
    wmma::fill_fragment(acc[1], 0.f);

    auto load_stage = [&](int s, int kt) {
        float* As = fcbuf + s * STG;
        float* Bs = As + BM * LDA;
        int k0 = kt * BK;
        #pragma unroll
        for (int t = 0; t < 2; t++) {          // A: 1024 float4
            int i = tid + t * 512;
            int r = i >> 3, c4 = i & 7;
            cp16(As + r * LDA + c4 * 4, g_cat + (size_t)(m0 + r) * NP + k0 + c4 * 4);
        }
        {                                      // B: 512 float4
            int r = tid >> 4, c4 = tid & 15;
            cp16(Bs + r * LDB + c4 * 4, g_wp + (size_t)(k0 + r) * NP + n0 + c4 * 4);
        }
        cp_commit();
    };

    load_stage(0, 0);
    for (int t = 0; t < NT; t++) {
        int s = t & 1;
        if (t + 1 < NT) { load_stage(s ^ 1, t + 1); cp_wait<1>(); }
        else            { cp_wait<0>(); }
        __syncthreads();
        const float* As = fcbuf + s * STG;
        const float* Bs = As + BM * LDA;
        #pragma unroll
        for (int kk = 0; kk < BK; kk += 8) {
            wmma::fragment<wmma::matrix_a, 16, 16, 8, wmma::precision::tf32, wmma::row_major> a;
            wmma::fragment<wmma::matrix_b, 16, 16, 8, wmma::precision::tf32, wmma::row_major> b0, b1;
            wmma::load_matrix_sync(a, As + (wm * 16) * LDA + kk, LDA);
            wmma::load_matrix_sync(b0, Bs + kk * LDB + wn * 32, LDB);
            wmma::load_matrix_sync(b1, Bs + kk * LDB + wn * 32 + 16, LDB);
            wmma::mma_sync(acc[0], a, b0, acc[0]);
            wmma::mma_sync(acc[1], a, b1, acc[1]);
        }
        __syncthreads();
    }

    float* Cs = fcbuf;                          // 128 x 68
    wmma::store_matrix_sync(Cs + (wm * 16) * LDB + wn * 32,      acc[0], LDB, wmma::mem_row_major);
    wmma::store_matrix_sync(Cs + (wm * 16) * LDB + wn * 32 + 16, acc[1], LDB, wmma::mem_row_major);
    __syncthreads();
    #pragma unroll
    for (int t = 0; t < 16; t++) {               // 128*64/512
        int i = tid + t * 512;
        int r = i >> 6, c = i & 63;
        int gr = m0 + r, gc = n0 + c;
        if (gr < N_DIM && gc < F_CNN) {
            float v = Cs[r * LDB + c] + bfc[gc];
            g_feat[(size_t)gr * F_CNN + gc] = v > 0.f ? v : 0.f;
        }
    }
}

// ---------------- pairs: outer product write (HBM-bound) ---------------------
#define NF2 621   // 1242/2

__global__ void k_pairs(float* __restrict__ out) {
    __shared__ float2 srna[NF2];
    int i = blockIdx.x;                 // 0..599
    int tid = threadIdx.x;              // 640
    const float2* rrow = (const float2*)(g_feat + (size_t)i * F_CNN);
    if (tid < NF2) srna[tid] = rrow[tid];
    __syncthreads();
    if (tid >= NF2) return;
    float2 rv = srna[tid];
    int j0 = blockIdx.y * 48;
    #pragma unroll 4
    for (int j = j0; j < j0 + 48; j++) {
        const float2* drow = (const float2*)(g_feat + (size_t)(R_DIM + j) * F_CNN);
        float2 dv = drow[tid];
        float2 o; o.x = rv.x * dv.x; o.y = rv.y * dv.y;
        __stcs((float2*)(out + (size_t)(i * D_DIM + j) * F_CNN) + tid, o);
    }
}

// ---------------- launch ------------------------------------------------------
extern "C" void kernel_launch(void* const* d_in, const int* in_sizes, int n_in,
                              void* d_out, int out_size) {
    const int*   ei   = (const int*)d_in[0];
    const float* met  = (const float*)d_in[1];
    const float* dis  = (const float*)d_in[2];
    const float* rel  = (const float*)d_in[3];
    const float* Wr   = (const float*)d_in[4];
    const float* Wd   = (const float*)d_in[5];
    const float* Wl   = (const float*)d_in[6];
    const float* bl   = (const float*)d_in[7];
    const float* Wrt  = (const float*)d_in[8];
    const float* br   = (const float*)d_in[9];
    const float* att  = (const float*)d_in[10];
    const float* gb   = (const float*)d_in[11];
    const float* c1w  = (const float*)d_in[12];
    const float* c1b  = (const float*)d_in[13];
    const float* c4w  = (const float*)d_in[14];
    const float* c4b  = (const float*)d_in[15];
    const float* c16w = (const float*)d_in[16];
    const float* c16b = (const float*)d_in[17];
    const float* c32w = (const float*)d_in[18];
    const float* c32b = (const float*)d_in[19];
    const float* Wfc  = (const float*)d_in[20];
    const float* bfc  = (const float*)d_in[21];
    float* out = (float*)d_out;

    static int smem_set = 0;
    if (!smem_set) {
        cudaFuncSetAttribute(k_fc, cudaFuncAttributeMaxDynamicSharedMemorySize, FC_SMEM);
        smem_set = 1;
    }

    size_t labels_off = (size_t)out_size - (size_t)R_DIM * D_DIM;
    int pad_total = KP * NP + (MP - N_DIM) * NP + R_DIM * D_DIM;

    // order chosen so ncu's captured launch (index 3) is k_gatconv
    k_prep<<<1, 1024>>>(ei);
    k_hx<<<105, 512>>>(met, dis, Wr, Wd, Wl, bl, Wrt, br);
    k_logits<<<(ME * 32 + 255) / 256, 256>>>(ei, att);
    k_gatconv<<<N_DIM, 256>>>(ei, gb, c1w, c1b, c4w, c4b, c16w, c16b, c32w, c32b);
    k_pad<<<(pad_total + 255) / 256, 256>>>(Wfc, rel, out, labels_off);
    k_fc<<<dim3(NP / BN, MP / BM), 512, FC_SMEM>>>(bfc);
    k_pairs<<<dim3(R_DIM, 5), 640>>>(out);
}